// round 6
// baseline (speedup 1.0000x reference)
#include <cuda_runtime.h>
#include <cuda_fp16.h>
#include <cstdint>
#include <cstring>

#define Bsz 32
#define Ssz 4096
#define Dsz 1280
#define Rsz 64

// fp16 pre-rounded concatenated params
__device__ __half g_Acat[8 * 128 * Dsz];          // [e][n(128)][k(1280)]
__device__ __half g_Bcat[8 * Dsz * 128];          // [e][d(1280)][k(128)]

#define STGA 18432          // 128 rows x 144B (64 halves + pad)
#define STGH 34816          // 128 rows x 272B (128 halves + pad)

// smem layout (bytes from dynamic base):
//  phase 1:  sX ring 2 x STGA @ [0, 36864)
//            sA ring 3 x STGA @ [36864, 92160)
//  phase 2:  sH (H tile)      @ [36864, 71680)   (aliases dead sA)
//            sB0              @ [0, 34816)       (aliases dead sX)
//            sB1              @ [71680, 106496)  (aliases dead sA upper)
#define OFF_X  0
#define OFF_A  36864
#define OFF_H  36864
#define OFF_B0 0
#define OFF_B1 71680
#define SMEM_TOTAL 106496

// ---------------------------------------------------------------------------
__device__ __forceinline__ uint32_t smem_u32(const void* p) {
    uint32_t a;
    asm("{ .reg .u64 t; cvta.to.shared.u64 t, %1; cvt.u32.u64 %0, t; }" : "=r"(a) : "l"(p));
    return a;
}
__device__ __forceinline__ unsigned h2u(__half2 h) {
    unsigned u; memcpy(&u, &h, 4); return u;
}
__device__ __forceinline__ void cp16(uint32_t dst, const void* src) {
    asm volatile("cp.async.cg.shared.global [%0], [%1], 16;" :: "r"(dst), "l"(src));
}
__device__ __forceinline__ void commit_group() {
    asm volatile("cp.async.commit_group;" ::: "memory");
}
__device__ __forceinline__ void sts128(uint32_t a, unsigned u0, unsigned u1, unsigned u2, unsigned u3) {
    asm volatile("st.shared.v4.b32 [%0], {%1,%2,%3,%4};" :: "r"(a), "r"(u0), "r"(u1), "r"(u2), "r"(u3));
}
__device__ __forceinline__ void sts32(uint32_t a, unsigned u) {
    asm volatile("st.shared.b32 [%0], %1;" :: "r"(a), "r"(u));
}
__device__ __forceinline__ void ldsm_x4(unsigned r[4], uint32_t addr) {
    asm volatile("ldmatrix.sync.aligned.m8n8.x4.shared.b16 {%0,%1,%2,%3}, [%4];"
                 : "=r"(r[0]), "=r"(r[1]), "=r"(r[2]), "=r"(r[3]) : "r"(addr));
}
__device__ __forceinline__ void mma16816(float c[4], const unsigned a[4], unsigned b0, unsigned b1) {
    asm volatile(
        "mma.sync.aligned.m16n8k16.row.col.f32.f16.f16.f32 "
        "{%0,%1,%2,%3}, {%4,%5,%6,%7}, {%8,%9}, {%0,%1,%2,%3};"
        : "+f"(c[0]), "+f"(c[1]), "+f"(c[2]), "+f"(c[3])
        : "r"(a[0]), "r"(a[1]), "r"(a[2]), "r"(a[3]), "r"(b0), "r"(b1));
}

// ---------------------------------------------------------------------------
// Pre-convert params to fp16 concatenated layouts (rn rounding).
// ---------------------------------------------------------------------------
__global__ void preconv_kernel(const float* __restrict__ A_exp,
                               const float* __restrict__ B_exp,
                               const float* __restrict__ A_gen,
                               const float* __restrict__ B_gen)
{
    int idx = blockIdx.x * blockDim.x + threadIdx.x;
    const int NA = 8 * 128 * Dsz / 2;
    if (idx < NA) {
        int p = idx * 2;
        int e = p / (128 * Dsz);
        int r = p % (128 * Dsz);
        int n = r / Dsz, k = r % Dsz;
        float f0, f1;
        if (n < Rsz) {
            const float* s = A_exp + ((size_t)e * Rsz + n) * Dsz + k;
            f0 = s[0]; f1 = s[1];
        } else {
            const float* s = A_gen + (size_t)(n - Rsz) * Dsz + k;
            f0 = s[0]; f1 = s[1];
        }
        *reinterpret_cast<__half2*>(&g_Acat[p]) = __floats2half2_rn(f0, f1);

        int e2 = p / (Dsz * 128);
        int r2 = p % (Dsz * 128);
        int d = r2 / 128, k2 = r2 % 128;
        float g0, g1;
        if (k2 < Rsz) {
            const float* s = B_exp + ((size_t)e2 * Dsz + d) * Rsz + k2;
            g0 = s[0]; g1 = s[1];
        } else {
            const float* s = B_gen + (size_t)d * Rsz + (k2 - Rsz);
            g0 = s[0]; g1 = s[1];
        }
        *reinterpret_cast<__half2*>(&g_Bcat[p]) = __floats2half2_rn(g0, g1);
    }
}

// ---------------------------------------------------------------------------
// Fused kernel: per (m-tile, b) CTA
//   phase 1: Ht (128x128 fp16, smem) = x_tile @ Acat[e]^T
//   phase 2: out_tile (128x1280)     = 2 * Ht @ Bcat[e]^T
// grid (32, 32), 256 thr (8 warps, 4M x 2N, warp tile 32x64).
// b == 31: zero the output slice (reference loops range(B-1)).
// ---------------------------------------------------------------------------
__global__ __launch_bounds__(256) void fused_lora(
    const float* __restrict__ x,
    const int*   __restrict__ label,
    float*       __restrict__ out)
{
    extern __shared__ char smem[];
    const int b   = blockIdx.y;
    const int m0  = blockIdx.x * 128;
    const int tid = threadIdx.x;

    float* ob = out + ((size_t)b * Ssz + m0) * Dsz;

    if (b == Bsz - 1) {
        float4 z = make_float4(0.f, 0.f, 0.f, 0.f);
#pragma unroll 4
        for (int i = 0; i < 160; i++) {
            int v = tid + i * 256;       // 40960 float4 = 128 rows x 320
            int row = v / 320, c4 = v % 320;
            __stcs((float4*)(ob + (size_t)row * Dsz + c4 * 4), z);
        }
        return;
    }

    const int e = __ldg(&label[b]);
    const int warp = tid >> 5, lane = tid & 31;
    const int wm = warp & 3, wn = warp >> 2;
    const int lg = lane >> 2, lc = lane & 3;

    uint32_t base = smem_u32(smem);
    uint32_t sX = base + OFF_X;
    uint32_t sA = base + OFF_A;
    uint32_t sH = base + OFF_H;

    const char* xb = (const char*)(x + ((size_t)b * Ssz + m0) * Dsz);
    const char* Ab = (const char*)g_Acat + (size_t)e * 128 * Dsz * 2;

    // ===================== phase 1 =====================
    // ldmatrix per-lane offsets (stride 144)
    uint32_t aoff[2], boff[4];
#pragma unroll
    for (int i = 0; i < 2; i++)
        aoff[i] = (uint32_t)((wm * 32 + i * 16 + (lane & 15)) * 144 + ((lane >> 4) << 4));
#pragma unroll
    for (int jp = 0; jp < 4; jp++)
        boff[jp] = (uint32_t)((wn * 64 + jp * 16 + (lane & 7) + ((lane >> 4) << 3)) * 144
                              + (((lane >> 3) & 1) << 4));

    auto cp_A = [&](int j) {
        uint32_t dst = sA + (j % 3) * STGA;
        const char* bsrc = Ab + (size_t)j * 128;
#pragma unroll
        for (int i = 0; i < 4; i++) {
            int cid = tid + i * 256;
            int row = cid >> 3, g = cid & 7;
            cp16(dst + row * 144 + g * 16, bsrc + (size_t)row * (Dsz * 2) + g * 16);
        }
        commit_group();
    };

    auto produce_x = [&](int j) {
        uint32_t dst = sX + (j & 1) * STGA;
        float4 v[8];
#pragma unroll
        for (int q = 0; q < 4; q++) {
            int cid = tid + q * 256;
            int row = cid >> 3, gp = cid & 7;
            const float4* src = (const float4*)(xb + (size_t)row * (Dsz * 4) + j * 256 + gp * 32);
            v[q * 2]     = __ldg(src);
            v[q * 2 + 1] = __ldg(src + 1);
        }
#pragma unroll
        for (int q = 0; q < 4; q++) {
            int cid = tid + q * 256;
            int row = cid >> 3, gp = cid & 7;
            unsigned u0 = h2u(__floats2half2_rn(v[q*2].x,   v[q*2].y));
            unsigned u1 = h2u(__floats2half2_rn(v[q*2].z,   v[q*2].w));
            unsigned u2 = h2u(__floats2half2_rn(v[q*2+1].x, v[q*2+1].y));
            unsigned u3 = h2u(__floats2half2_rn(v[q*2+1].z, v[q*2+1].w));
            sts128(dst + row * 144 + gp * 16, u0, u1, u2, u3);
        }
    };

    cp_A(0);
    cp_A(1);
    produce_x(0);
    asm volatile("cp.async.wait_group 1;" ::: "memory");
    __syncthreads();

    {
        float acc[2][8][4] = {};

        const int KT = Dsz / 64;    // 20
#pragma unroll 1
        for (int kt = 0; kt < KT; kt++) {
            if (kt + 2 < KT) cp_A(kt + 2);
            else             commit_group();
            if (kt + 1 < KT) produce_x(kt + 1);

            uint32_t aS = sX + (kt & 1) * STGA;
            uint32_t bS = sA + (kt % 3) * STGA;

#pragma unroll
            for (int kk = 0; kk < 4; kk++) {
                unsigned af[2][4], bf[4][4];
                uint32_t kb = kk * 32;
#pragma unroll
                for (int i = 0; i < 2; i++) ldsm_x4(af[i], aS + aoff[i] + kb);
#pragma unroll
                for (int jp = 0; jp < 4; jp++) ldsm_x4(bf[jp], bS + boff[jp] + kb);
#pragma unroll
                for (int i = 0; i < 2; i++)
#pragma unroll
                    for (int jp = 0; jp < 4; jp++) {
                        mma16816(acc[i][2*jp],   af[i], bf[jp][0], bf[jp][1]);
                        mma16816(acc[i][2*jp+1], af[i], bf[jp][2], bf[jp][3]);
                    }
            }
            asm volatile("cp.async.wait_group 1;" ::: "memory");
            __syncthreads();
        }

        // H epilogue -> smem (fp16, stride 272). All phase-1 buffers now dead.
#pragma unroll
        for (int i = 0; i < 2; i++) {
            int r = wm * 32 + i * 16 + lg;
#pragma unroll
            for (int j = 0; j < 8; j++) {
                int c = wn * 64 + j * 8 + lc * 2;
                sts32(sH + (uint32_t)(r * 272 + c * 2),
                      h2u(__floats2half2_rn(acc[i][j][0], acc[i][j][1])));
                sts32(sH + (uint32_t)((r + 8) * 272 + c * 2),
                      h2u(__floats2half2_rn(acc[i][j][2], acc[i][j][3])));
            }
        }
    }
    __syncthreads();

    // ===================== phase 2 =====================
    // ldmatrix per-lane offsets (stride 272)
    uint32_t aoff2[2], boff2[4];
#pragma unroll
    for (int i = 0; i < 2; i++)
        aoff2[i] = (uint32_t)((wm * 32 + i * 16 + (lane & 15)) * 272 + ((lane >> 4) << 4));
#pragma unroll
    for (int jp = 0; jp < 4; jp++)
        boff2[jp] = (uint32_t)((wn * 64 + jp * 16 + (lane & 7) + ((lane >> 4) << 3)) * 272
                               + (((lane >> 3) & 1) << 4));

    uint32_t sBs[2] = { base + OFF_B0, base + OFF_B1 };

    auto cp_B = [&](int nt) {
        uint32_t dst = sBs[nt & 1];
        const char* bsrc = (const char*)g_Bcat + ((size_t)e * Dsz + nt * 128) * 256;
#pragma unroll
        for (int i = 0; i < 8; i++) {
            int cid = tid + i * 256;
            int row = cid >> 4, g = cid & 15;
            cp16(dst + row * 272 + g * 16, bsrc + (size_t)row * 256 + g * 16);
        }
        commit_group();
    };

    cp_B(0);
    cp_B(1);
    asm volatile("cp.async.wait_group 1;" ::: "memory");
    __syncthreads();

#pragma unroll 1
    for (int nt = 0; nt < 10; nt++) {
        float acc[2][8][4] = {};
        uint32_t bS = sBs[nt & 1];

#pragma unroll
        for (int kk = 0; kk < 8; kk++) {
            unsigned af[2][4], bf[4][4];
            uint32_t kb = kk * 32;
#pragma unroll
            for (int i = 0; i < 2; i++) ldsm_x4(af[i], sH + aoff2[i] + kb);
#pragma unroll
            for (int jp = 0; jp < 4; jp++) ldsm_x4(bf[jp], bS + boff2[jp] + kb);
#pragma unroll
            for (int i = 0; i < 2; i++)
#pragma unroll
                for (int jp = 0; jp < 4; jp++) {
                    mma16816(acc[i][2*jp],   af[i], bf[jp][0], bf[jp][1]);
                    mma16816(acc[i][2*jp+1], af[i], bf[jp][2], bf[jp][3]);
                }
        }

        __syncthreads();                       // ldsm of this stage done
        if (nt + 2 < 10) cp_B(nt + 2);         // refill freed slot
        else             commit_group();       // keep accounting uniform

        // epilogue overlaps the B prefetch
        int n0 = nt * 128;
#pragma unroll
        for (int i = 0; i < 2; i++) {
            int r = wm * 32 + i * 16 + lg;
#pragma unroll
            for (int j = 0; j < 8; j++) {
                int c = n0 + wn * 64 + j * 8 + lc * 2;
                __stcs((float2*)&ob[(size_t)r * Dsz + c],
                       make_float2(2.0f * acc[i][j][0], 2.0f * acc[i][j][1]));
                __stcs((float2*)&ob[(size_t)(r + 8) * Dsz + c],
                       make_float2(2.0f * acc[i][j][2], 2.0f * acc[i][j][3]));
            }
        }

        asm volatile("cp.async.wait_group 1;" ::: "memory");   // B(nt+1) complete
        __syncthreads();
    }
}

// ---------------------------------------------------------------------------
extern "C" void kernel_launch(void* const* d_in, const int* in_sizes, int n_in,
                              void* d_out, int out_size)
{
    const float* x     = (const float*)d_in[0];
    // d_in[1] = weight : unused by the reference
    const float* A_exp = (const float*)d_in[2];
    const float* B_exp = (const float*)d_in[3];
    const float* A_gen = (const float*)d_in[4];
    const float* B_gen = (const float*)d_in[5];
    const int*   label = (const int*)d_in[6];
    float* out = (float*)d_out;

    cudaFuncSetAttribute(fused_lora, cudaFuncAttributeMaxDynamicSharedMemorySize, SMEM_TOTAL);

    preconv_kernel<<<(8 * 128 * Dsz / 2 + 255) / 256, 256>>>(A_exp, B_exp, A_gen, B_gen);
    fused_lora<<<dim3(Ssz / 128, Bsz), 256, SMEM_TOTAL>>>(x, label, out);
}

// round 7
// speedup vs baseline: 1.1700x; 1.1700x over previous
#include <cuda_runtime.h>
#include <cuda_fp16.h>
#include <cstdint>
#include <cstring>

#define Bsz 32
#define Ssz 4096
#define Dsz 1280
#define Rsz 64

// fp16 scratch: concatenated pre-rounded params + intermediate H
__device__ __half g_Acat[8 * 128 * Dsz];          // [e][n(128)][k(1280)]
__device__ __half g_Bcat[8 * Dsz * 128];          // [e][d(1280)][k(128)]
__device__ __half g_H[31u * Ssz * 128];           // [b][m][k(128)]

#define STGA 18432          // 128 rows x 144B (64 halves + pad)
#define STGH 34816          // 128 rows x 272B (128 halves + pad)
#define SMEM1 (2 * STGA + 3 * STGA)    // 92160
#define SMEM2 (STGH + 2 * STGH)        // 104448

// ---------------------------------------------------------------------------
__device__ __forceinline__ uint32_t smem_u32(const void* p) {
    uint32_t a;
    asm("{ .reg .u64 t; cvta.to.shared.u64 t, %1; cvt.u32.u64 %0, t; }" : "=r"(a) : "l"(p));
    return a;
}
__device__ __forceinline__ unsigned h2u(__half2 h) {
    unsigned u; memcpy(&u, &h, 4); return u;
}
__device__ __forceinline__ void cp16(uint32_t dst, const void* src) {
    asm volatile("cp.async.cg.shared.global [%0], [%1], 16;" :: "r"(dst), "l"(src));
}
__device__ __forceinline__ void commit_group() {
    asm volatile("cp.async.commit_group;" ::: "memory");
}
__device__ __forceinline__ void sts128(uint32_t a, unsigned u0, unsigned u1, unsigned u2, unsigned u3) {
    asm volatile("st.shared.v4.b32 [%0], {%1,%2,%3,%4};" :: "r"(a), "r"(u0), "r"(u1), "r"(u2), "r"(u3));
}
__device__ __forceinline__ void ldsm_x4(unsigned r[4], uint32_t addr) {
    asm volatile("ldmatrix.sync.aligned.m8n8.x4.shared.b16 {%0,%1,%2,%3}, [%4];"
                 : "=r"(r[0]), "=r"(r[1]), "=r"(r[2]), "=r"(r[3]) : "r"(addr));
}
__device__ __forceinline__ void mma16816(float c[4], const unsigned a[4], unsigned b0, unsigned b1) {
    asm volatile(
        "mma.sync.aligned.m16n8k16.row.col.f32.f16.f16.f32 "
        "{%0,%1,%2,%3}, {%4,%5,%6,%7}, {%8,%9}, {%0,%1,%2,%3};"
        : "+f"(c[0]), "+f"(c[1]), "+f"(c[2]), "+f"(c[3])
        : "r"(a[0]), "r"(a[1]), "r"(a[2]), "r"(a[3]), "r"(b0), "r"(b1));
}

// ---------------------------------------------------------------------------
// Pre-convert params to fp16 concatenated layouts (rn rounding).
// ---------------------------------------------------------------------------
__global__ void preconv_kernel(const float* __restrict__ A_exp,
                               const float* __restrict__ B_exp,
                               const float* __restrict__ A_gen,
                               const float* __restrict__ B_gen)
{
    int idx = blockIdx.x * blockDim.x + threadIdx.x;
    const int NA = 8 * 128 * Dsz / 2;
    if (idx < NA) {
        int p = idx * 2;
        int e = p / (128 * Dsz);
        int r = p % (128 * Dsz);
        int n = r / Dsz, k = r % Dsz;
        float f0, f1;
        if (n < Rsz) {
            const float* s = A_exp + ((size_t)e * Rsz + n) * Dsz + k;
            f0 = s[0]; f1 = s[1];
        } else {
            const float* s = A_gen + (size_t)(n - Rsz) * Dsz + k;
            f0 = s[0]; f1 = s[1];
        }
        *reinterpret_cast<__half2*>(&g_Acat[p]) = __floats2half2_rn(f0, f1);

        int e2 = p / (Dsz * 128);
        int r2 = p % (Dsz * 128);
        int d = r2 / 128, k2 = r2 % 128;
        float g0, g1;
        if (k2 < Rsz) {
            const float* s = B_exp + ((size_t)e2 * Dsz + d) * Rsz + k2;
            g0 = s[0]; g1 = s[1];
        } else {
            const float* s = B_gen + (size_t)d * Rsz + (k2 - Rsz);
            g0 = s[0]; g1 = s[1];
        }
        *reinterpret_cast<__half2*>(&g_Bcat[p]) = __floats2half2_rn(g0, g1);
    }
}

// ---------------------------------------------------------------------------
// GEMM1: H[b] (4096x128) = x[b] @ Acat[b]^T, fp16 mma, output fp16 to g_H.
// grid (32, 31), 256 thr (8 warps 4Mx2N, warp tile 32x64). K-stage 64, KT=20.
// x producer decoupled: LDG+cvt issued one full iteration before its STS.
// ---------------------------------------------------------------------------
__global__ __launch_bounds__(256, 2) void gemm1_fp16(
    const float* __restrict__ x,
    const int*   __restrict__ label)
{
    extern __shared__ char smem[];
    const int b   = blockIdx.y;
    const int m0  = blockIdx.x * 128;
    const int e   = __ldg(&label[b]);
    const int tid = threadIdx.x;
    const int warp = tid >> 5, lane = tid & 31;
    const int wm = warp & 3, wn = warp >> 2;
    const int lg = lane >> 2, lc = lane & 3;

    uint32_t sX = smem_u32(smem);                 // x ring: 2 stages
    uint32_t sA = sX + 2 * STGA;                  // Acat ring: 3 stages

    const char* xb = (const char*)(x + ((size_t)b * Ssz + m0) * Dsz);
    const char* Ab = (const char*)g_Acat + (size_t)e * 128 * Dsz * 2;

    // ldmatrix per-lane offsets (stride 144)
    uint32_t aoff[2], boff[4];
#pragma unroll
    for (int i = 0; i < 2; i++)
        aoff[i] = (uint32_t)((wm * 32 + i * 16 + (lane & 15)) * 144 + ((lane >> 4) << 4));
#pragma unroll
    for (int jp = 0; jp < 4; jp++)
        boff[jp] = (uint32_t)((wn * 64 + jp * 16 + (lane & 7) + ((lane >> 4) << 3)) * 144
                              + (((lane >> 3) & 1) << 4));

    auto cp_A = [&](int j) {
        uint32_t dst = sA + (j % 3) * STGA;
        const char* base = Ab + (size_t)j * 128;   // k-slice: 64 halves = 128B
#pragma unroll
        for (int i = 0; i < 4; i++) {
            int cid = tid + i * 256;               // 1024 chunks
            int row = cid >> 3, g = cid & 7;
            cp16(dst + row * 144 + g * 16, base + (size_t)row * (Dsz * 2) + g * 16);
        }
        commit_group();
    };

    // x pipeline registers: 16 half2 = one stage's worth per thread
    unsigned xu[16];

    auto ldg_x = [&](int j) {   // LDG fp32 + cvt to half2 regs (no smem write)
#pragma unroll
        for (int q = 0; q < 4; q++) {
            int cid = tid + q * 256;               // 1024 chunks
            int row = cid >> 3, gp = cid & 7;
            const float4* src = (const float4*)(xb + (size_t)row * (Dsz * 4) + j * 256 + gp * 32);
            float4 a = __ldg(src);
            float4 c = __ldg(src + 1);
            xu[q*4+0] = h2u(__floats2half2_rn(a.x, a.y));
            xu[q*4+1] = h2u(__floats2half2_rn(a.z, a.w));
            xu[q*4+2] = h2u(__floats2half2_rn(c.x, c.y));
            xu[q*4+3] = h2u(__floats2half2_rn(c.z, c.w));
        }
    };
    auto sts_x = [&](int j) {
        uint32_t dst = sX + (j & 1) * STGA;
#pragma unroll
        for (int q = 0; q < 4; q++) {
            int cid = tid + q * 256;
            int row = cid >> 3, gp = cid & 7;
            sts128(dst + row * 144 + gp * 16, xu[q*4+0], xu[q*4+1], xu[q*4+2], xu[q*4+3]);
        }
    };

    // prologue
    cp_A(0);
    cp_A(1);
    ldg_x(0);
    sts_x(0);
    ldg_x(1);          // in flight; STS'd at end of kt=0
    asm volatile("cp.async.wait_group 1;" ::: "memory");
    __syncthreads();

    float acc[2][8][4] = {};

    const int KT = Dsz / 64;    // 20
#pragma unroll 1
    for (int kt = 0; kt < KT; kt++) {
        if (kt + 2 < KT) cp_A(kt + 2);
        else             commit_group();

        uint32_t aS = sX + (kt & 1) * STGA;
        uint32_t bS = sA + (kt % 3) * STGA;

#pragma unroll
        for (int kk = 0; kk < 4; kk++) {
            unsigned af[2][4], bf[4][4];
            uint32_t kb = kk * 32;
#pragma unroll
            for (int i = 0; i < 2; i++) ldsm_x4(af[i], aS + aoff[i] + kb);
#pragma unroll
            for (int jp = 0; jp < 4; jp++) ldsm_x4(bf[jp], bS + boff[jp] + kb);
#pragma unroll
            for (int i = 0; i < 2; i++)
#pragma unroll
                for (int jp = 0; jp < 4; jp++) {
                    mma16816(acc[i][2*jp],   af[i], bf[jp][0], bf[jp][1]);
                    mma16816(acc[i][2*jp+1], af[i], bf[jp][2], bf[jp][3]);
                }
        }

        // x stage kt+1 was LDG'd last iteration: store it now (latency hidden)
        if (kt + 1 < KT) sts_x(kt + 1);
        if (kt + 2 < KT) ldg_x(kt + 2);

        asm volatile("cp.async.wait_group 1;" ::: "memory");
        __syncthreads();
    }

    // epilogue: H (fp16) -> global
    __half* Hb = g_H + ((size_t)b * Ssz + m0) * 128;
#pragma unroll
    for (int i = 0; i < 2; i++) {
        int r = wm * 32 + i * 16 + lg;
#pragma unroll
        for (int j = 0; j < 8; j++) {
            int c = wn * 64 + j * 8 + lc * 2;
            *reinterpret_cast<__half2*>(Hb + (size_t)r * 128 + c) =
                __floats2half2_rn(acc[i][j][0], acc[i][j][1]);
            *reinterpret_cast<__half2*>(Hb + (size_t)(r + 8) * 128 + c) =
                __floats2half2_rn(acc[i][j][2], acc[i][j][3]);
        }
    }
}

// ---------------------------------------------------------------------------
// GEMM2: out[b] (4096x1280) = 2 * H[b] @ Bcat[b]^T.
// grid (32, 32), 256 thr. H tile in smem once; loop 10 n-tiles, B ring 2 stages.
// B prefetch overlapped with epilogue stores. b==31 CTAs zero their slice.
// ---------------------------------------------------------------------------
__global__ __launch_bounds__(256, 2) void gemm2_fp16(
    const int* __restrict__ label,
    float*     __restrict__ out)
{
    extern __shared__ char smem[];
    const int b   = blockIdx.y;
    const int m0  = blockIdx.x * 128;
    const int tid = threadIdx.x;

    float* ob = out + ((size_t)b * Ssz + m0) * Dsz;

    if (b == Bsz - 1) {
        float4 z = make_float4(0.f, 0.f, 0.f, 0.f);
#pragma unroll 4
        for (int i = 0; i < 160; i++) {
            int v = tid + i * 256;       // 40960 float4 = 128 rows x 320
            int row = v / 320, c4 = v % 320;
            __stcs((float4*)(ob + (size_t)row * Dsz + c4 * 4), z);
        }
        return;
    }

    const int e = __ldg(&label[b]);
    const int warp = tid >> 5, lane = tid & 31;
    const int wm = warp & 3, wn = warp >> 2;
    const int lg = lane >> 2, lc = lane & 3;

    uint32_t sH = smem_u32(smem);
    uint32_t sB = sH + STGH;

    // ldmatrix per-lane offsets (stride 272)
    uint32_t aoff[2], boff[4];
#pragma unroll
    for (int i = 0; i < 2; i++)
        aoff[i] = (uint32_t)((wm * 32 + i * 16 + (lane & 15)) * 272 + ((lane >> 4) << 4));
#pragma unroll
    for (int jp = 0; jp < 4; jp++)
        boff[jp] = (uint32_t)((wn * 64 + jp * 16 + (lane & 7) + ((lane >> 4) << 3)) * 272
                              + (((lane >> 3) & 1) << 4));

    // H tile load (once)
    {
        const char* base = (const char*)g_H + ((size_t)b * Ssz + m0) * 256;
#pragma unroll
        for (int i = 0; i < 8; i++) {
            int cid = tid + i * 256;               // 2048 chunks
            int row = cid >> 4, g = cid & 15;
            cp16(sH + row * 272 + g * 16, base + (size_t)row * 256 + g * 16);
        }
        commit_group();
    }

    auto cp_B = [&](int nt) {
        uint32_t dst = sB + (nt & 1) * STGH;
        const char* base = (const char*)g_Bcat + ((size_t)e * Dsz + nt * 128) * 256;
#pragma unroll
        for (int i = 0; i < 8; i++) {
            int cid = tid + i * 256;
            int row = cid >> 4, g = cid & 15;
            cp16(dst + row * 272 + g * 16, base + (size_t)row * 256 + g * 16);
        }
        commit_group();
    };

    cp_B(0);
    cp_B(1);
    asm volatile("cp.async.wait_group 1;" ::: "memory");   // H + B0 ready
    __syncthreads();

#pragma unroll 1
    for (int nt = 0; nt < 10; nt++) {
        float acc[2][8][4] = {};
        uint32_t bS = sB + (nt & 1) * STGH;

#pragma unroll
        for (int kk = 0; kk < 8; kk++) {
            unsigned af[2][4], bf[4][4];
            uint32_t kb = kk * 32;
#pragma unroll
            for (int i = 0; i < 2; i++) ldsm_x4(af[i], sH + aoff[i] + kb);
#pragma unroll
            for (int jp = 0; jp < 4; jp++) ldsm_x4(bf[jp], bS + boff[jp] + kb);
#pragma unroll
            for (int i = 0; i < 2; i++)
#pragma unroll
                for (int jp = 0; jp < 4; jp++) {
                    mma16816(acc[i][2*jp],   af[i], bf[jp][0], bf[jp][1]);
                    mma16816(acc[i][2*jp+1], af[i], bf[jp][2], bf[jp][3]);
                }
        }

        __syncthreads();                      // all warps done reading slot nt&1
        if (nt + 2 < 10) cp_B(nt + 2);        // refill freed slot, overlaps epilogue
        else             commit_group();

        // epilogue for this n-tile: out = 2*acc (hides B transfer)
        int n0 = nt * 128;
#pragma unroll
        for (int i = 0; i < 2; i++) {
            int r = wm * 32 + i * 16 + lg;
#pragma unroll
            for (int j = 0; j < 8; j++) {
                int c = n0 + wn * 64 + j * 8 + lc * 2;
                __stcs((float2*)&ob[(size_t)r * Dsz + c],
                       make_float2(2.0f * acc[i][j][0], 2.0f * acc[i][j][1]));
                __stcs((float2*)&ob[(size_t)(r + 8) * Dsz + c],
                       make_float2(2.0f * acc[i][j][2], 2.0f * acc[i][j][3]));
            }
        }

        asm volatile("cp.async.wait_group 1;" ::: "memory");   // B(nt+1) complete
        __syncthreads();
    }
}

// ---------------------------------------------------------------------------
extern "C" void kernel_launch(void* const* d_in, const int* in_sizes, int n_in,
                              void* d_out, int out_size)
{
    const float* x     = (const float*)d_in[0];
    // d_in[1] = weight : unused by the reference
    const float* A_exp = (const float*)d_in[2];
    const float* B_exp = (const float*)d_in[3];
    const float* A_gen = (const float*)d_in[4];
    const float* B_gen = (const float*)d_in[5];
    const int*   label = (const int*)d_in[6];
    float* out = (float*)d_out;

    cudaFuncSetAttribute(gemm1_fp16, cudaFuncAttributeMaxDynamicSharedMemorySize, SMEM1);
    cudaFuncSetAttribute(gemm2_fp16, cudaFuncAttributeMaxDynamicSharedMemorySize, SMEM2);

    preconv_kernel<<<(8 * 128 * Dsz / 2 + 255) / 256, 256>>>(A_exp, B_exp, A_gen, B_gen);
    gemm1_fp16<<<dim3(Ssz / 128, Bsz - 1), 256, SMEM1>>>(x, label);
    gemm2_fp16<<<dim3(Ssz / 128, Bsz), 256, SMEM2>>>(label, out);
}